// round 4
// baseline (speedup 1.0000x reference)
#include <cuda_runtime.h>
#include <math.h>

// Problem constants
#define B_    256
#define T_    512
#define I_    256
#define H_    1024
#define G4    4096   // 4*H
#define KTOT  1280   // I + H
#define OUT_  4
#define DEC1  512    // H/2

// Tiling for the per-step GEMM
#define TM 128
#define TN 64
#define TK 32
#define AS 36   // smem row stride (floats) for A/B tiles (16B-aligned: 36*4=144=16*9)
#define GS 68   // smem row stride for epilogue gate tile

// -------- scratch (static device allocations; harness-legal) --------
__device__ float g_Wcat[(size_t)G4 * KTOT];   // 20 MB permuted [W_ih | W_hh], pre-rounded to tf32
__device__ float g_bias[G4];                  // permuted b_ih + b_hh
__device__ float g_h[2][(size_t)B_ * H_];     // ping-pong hidden state
__device__ float g_c[(size_t)B_ * H_];        // cell state (in-place safe)
__device__ float g_y1[(size_t)B_ * DEC1];     // decoder intermediate

__device__ __forceinline__ unsigned f2tf(float f) {
    unsigned r;
    asm("cvt.rna.tf32.f32 %0, %1;" : "=r"(r) : "f"(f));
    return r;
}

// ====================================================================
// Prep: build gate-interleaved weight matrix, PRE-ROUNDED to tf32.
// Row n' of Wcat corresponds to gate (n'&3) of hidden column (n'>>2):
//   Wcat[n'][k] = tf32(W_ih[src][k])     for k <  I_
//              = tf32(W_hh[src][k - I_]) for k >= I_
// with src = (n'&3)*H + (n'>>2). Gate interleaving makes each 4-column
// group of the GEMM output a complete (i,f,g,o) quadruple -> the LSTM
// pointwise update fuses into the GEMM epilogue. Pre-rounding lets the
// mainloop feed B operands as raw bits (bit-identical to cvt per use).
// ====================================================================
__global__ void prep_w(const float* __restrict__ W_ih, const float* __restrict__ W_hh,
                       const float* __restrict__ b_ih, const float* __restrict__ b_hh) {
    int n = blockIdx.x;                 // 0..4095 (permuted row)
    int gate = n & 3, hcol = n >> 2;
    int src = gate * H_ + hcol;
    const float* wi = W_ih + (size_t)src * I_;
    const float* wh = W_hh + (size_t)src * H_;
    float* dst = g_Wcat + (size_t)n * KTOT;
    for (int k = threadIdx.x; k < KTOT; k += blockDim.x) {
        float v = (k < I_) ? wi[k] : wh[k - I_];
        unsigned u = f2tf(v);
        dst[k] = __uint_as_float(u);
    }
    if (threadIdx.x == 0) g_bias[n] = b_ih[src] + b_hh[src];
}

__global__ void prep_state(const float* __restrict__ h0, const float* __restrict__ c0) {
    int i = blockIdx.x * blockDim.x + threadIdx.x;
    if (i < B_ * H_) { g_h[0][i] = h0[i]; g_c[i] = c0[i]; }
}

// ====================================================================
// One LSTM step: g = [x_t | h_prev] @ Wcat^T ; pointwise update fused.
// grid = (64 n-tiles, 2 m-tiles), 256 threads (8 warps as 4m x 2n of 32x32).
// TF32 mma.sync m16n8k8, fp32 accumulate.
// ====================================================================
__global__ __launch_bounds__(256) void lstm_step(const float* __restrict__ x,
                                                 int t, int pp) {
    __shared__ float sm[TM * GS];        // 34816 B; A/B tiles and gate tile alias
    float* As = sm;                      // [128][AS]
    float* Bs = sm + TM * AS;            // [64][AS]

    const float* hprev = g_h[pp];
    float*       hnext = g_h[pp ^ 1];

    int tid   = threadIdx.x;
    int ntile = blockIdx.x;              // 0..63
    int mtile = blockIdx.y;              // 0..1
    int warp = tid >> 5, lane = tid & 31;
    int wm = warp & 3, wn = warp >> 2;   // warp tile position
    int g  = lane >> 2, tg = lane & 3;   // mma lane coords

    float acc[2][4][4];
    #pragma unroll
    for (int a = 0; a < 2; a++)
        #pragma unroll
        for (int b = 0; b < 4; b++)
            #pragma unroll
            for (int c = 0; c < 4; c++) acc[a][b][c] = 0.f;

    int r8 = tid >> 3;                   // 0..31 (loader row base)
    int k4 = (tid & 7) * 4;              // 0..28 (loader k offset)

    for (int k0 = 0; k0 < KTOT; k0 += TK) {
        __syncthreads();
        // ---- load A tile: [x_t | h_prev], 128 x 32 ----
        #pragma unroll
        for (int j = 0; j < 4; j++) {
            int r = r8 + j * 32;
            int b = mtile * TM + r;
            const float* src = (k0 < I_)
                ? x + (size_t)b * (T_ * I_) + (size_t)t * I_ + (k0 + k4)
                : hprev + (size_t)b * H_ + (k0 - I_) + k4;
            float4 v = *(const float4*)src;
            *(float4*)&As[r * AS + k4] = v;
        }
        // ---- load B tile: Wcat (already tf32-rounded), 64 x 32 ----
        #pragma unroll
        for (int j = 0; j < 2; j++) {
            int r = r8 + j * 32;
            int n = ntile * TN + r;
            float4 v = *(const float4*)&g_Wcat[(size_t)n * KTOT + k0 + k4];
            *(float4*)&Bs[r * AS + k4] = v;
        }
        __syncthreads();
        // ---- 4 x k8 mma steps ----
        #pragma unroll
        for (int ks = 0; ks < 4; ks++) {
            int kk = ks * 8;
            unsigned af[2][4], bf[4][2];
            #pragma unroll
            for (int mi = 0; mi < 2; mi++) {
                int r0 = wm * 32 + mi * 16;
                af[mi][0] = f2tf(As[(r0 + g    ) * AS + kk + tg    ]);
                af[mi][1] = f2tf(As[(r0 + g + 8) * AS + kk + tg    ]);
                af[mi][2] = f2tf(As[(r0 + g    ) * AS + kk + tg + 4]);
                af[mi][3] = f2tf(As[(r0 + g + 8) * AS + kk + tg + 4]);
            }
            #pragma unroll
            for (int nj = 0; nj < 4; nj++) {
                int c0 = wn * 32 + nj * 8;
                bf[nj][0] = __float_as_uint(Bs[(c0 + g) * AS + kk + tg    ]);
                bf[nj][1] = __float_as_uint(Bs[(c0 + g) * AS + kk + tg + 4]);
            }
            #pragma unroll
            for (int mi = 0; mi < 2; mi++)
                #pragma unroll
                for (int nj = 0; nj < 4; nj++) {
                    asm volatile(
                        "mma.sync.aligned.m16n8k8.row.col.f32.tf32.tf32.f32 "
                        "{%0,%1,%2,%3}, {%4,%5,%6,%7}, {%8,%9}, {%0,%1,%2,%3};"
                        : "+f"(acc[mi][nj][0]), "+f"(acc[mi][nj][1]),
                          "+f"(acc[mi][nj][2]), "+f"(acc[mi][nj][3])
                        : "r"(af[mi][0]), "r"(af[mi][1]),
                          "r"(af[mi][2]), "r"(af[mi][3]),
                          "r"(bf[nj][0]), "r"(bf[nj][1]));
                }
        }
    }
    __syncthreads();

    // ---- spill gate tile to smem (128 x 64) ----
    float* Gs = sm;   // [128][GS]
    #pragma unroll
    for (int mi = 0; mi < 2; mi++) {
        int r0 = wm * 32 + mi * 16;
        #pragma unroll
        for (int nj = 0; nj < 4; nj++) {
            int c0 = wn * 32 + nj * 8 + tg * 2;
            Gs[(r0 + g    ) * GS + c0    ] = acc[mi][nj][0];
            Gs[(r0 + g    ) * GS + c0 + 1] = acc[mi][nj][1];
            Gs[(r0 + g + 8) * GS + c0    ] = acc[mi][nj][2];
            Gs[(r0 + g + 8) * GS + c0 + 1] = acc[mi][nj][3];
        }
    }
    __syncthreads();

    // ---- fused LSTM pointwise update: 128 rows x 16 hidden cols ----
    for (int it = tid; it < TM * 16; it += 256) {
        int r  = it >> 4;
        int j  = it & 15;
        int nl = 4 * j;
        int ng = ntile * TN + nl;
        float gi = Gs[r * GS + nl    ] + g_bias[ng    ];
        float gf = Gs[r * GS + nl + 1] + g_bias[ng + 1];
        float gg = Gs[r * GS + nl + 2] + g_bias[ng + 2];
        float go = Gs[r * GS + nl + 3] + g_bias[ng + 3];
        float iv = 1.f / (1.f + __expf(-gi));
        float fv = 1.f / (1.f + __expf(-gf));
        float gv = tanhf(gg);
        float ov = 1.f / (1.f + __expf(-go));
        int b  = mtile * TM + r;
        int hc = ntile * 16 + j;
        size_t idx = (size_t)b * H_ + hc;
        float c_new = fv * g_c[idx] + iv * gv;
        g_c[idx]   = c_new;
        hnext[idx] = ov * tanhf(c_new);
    }
}

// ====================================================================
// Decoder: y1 = h_T @ W1^T + b1 ; y = y1 @ W2^T + b2
// ====================================================================
__global__ void dec1(const float* __restrict__ W1, const float* __restrict__ b1) {
    __shared__ float hs[H_];
    int b = blockIdx.x;
    const float* h = g_h[0];   // after 512 steps the state is back in buffer 0
    for (int i = threadIdx.x; i < H_; i += blockDim.x) hs[i] = h[(size_t)b * H_ + i];
    __syncthreads();
    int warp = threadIdx.x >> 5, lane = threadIdx.x & 31;
    for (int m = warp; m < DEC1; m += 8) {
        const float* w = W1 + (size_t)m * H_;
        float s = 0.f;
        for (int k = lane; k < H_; k += 32) s += hs[k] * w[k];
        #pragma unroll
        for (int o = 16; o; o >>= 1) s += __shfl_down_sync(0xffffffffu, s, o);
        if (lane == 0) g_y1[(size_t)b * DEC1 + m] = s + b1[m];
    }
}

__global__ void dec2(const float* __restrict__ W2, const float* __restrict__ b2,
                     float* __restrict__ out) {
    int b = blockIdx.x;
    int warp = threadIdx.x >> 5, lane = threadIdx.x & 31;
    if (warp < OUT_) {
        const float* w = W2 + (size_t)warp * DEC1;
        const float* y = g_y1 + (size_t)b * DEC1;
        float s = 0.f;
        for (int k = lane; k < DEC1; k += 32) s += y[k] * w[k];
        #pragma unroll
        for (int o = 16; o; o >>= 1) s += __shfl_down_sync(0xffffffffu, s, o);
        if (lane == 0) out[b * OUT_ + warp] = s + b2[warp];
    }
}

// ====================================================================
extern "C" void kernel_launch(void* const* d_in, const int* in_sizes, int n_in,
                              void* d_out, int out_size) {
    const float* x    = (const float*)d_in[0];
    const float* h0   = (const float*)d_in[1];
    const float* c0   = (const float*)d_in[2];
    const float* W_ih = (const float*)d_in[3];
    const float* W_hh = (const float*)d_in[4];
    const float* b_ih = (const float*)d_in[5];
    const float* b_hh = (const float*)d_in[6];
    const float* W1   = (const float*)d_in[7];
    const float* b1   = (const float*)d_in[8];
    const float* W2   = (const float*)d_in[9];
    const float* b2   = (const float*)d_in[10];
    float* out = (float*)d_out;

    prep_w<<<G4, 256>>>(W_ih, W_hh, b_ih, b_hh);
    prep_state<<<(B_ * H_ + 511) / 512, 512>>>(h0, c0);

    dim3 grid(G4 / TN, B_ / TM);   // (64, 2)
    for (int t = 0; t < T_; t++)
        lstm_step<<<grid, 256>>>(x, t, t & 1);

    dec1<<<B_, 256>>>(W1, b1);
    dec2<<<B_, 128>>>(W2, b2, out);
}

// round 5
// speedup vs baseline: 1.5030x; 1.5030x over previous
#include <cuda_runtime.h>
#include <math.h>

// Problem constants
#define B_    256
#define T_    512
#define I_    256
#define H_    1024
#define G4    4096   // 4*H
#define KTOT  1280   // I + H
#define OUT_  4
#define DEC1  512    // H/2

// Tiling for the per-step GEMM
#define TM 128
#define TN 64
#define TK 32
#define NKIT (KTOT / TK)     // 40
#define STAGES 3
#define AS 36   // smem row stride (floats); 36*4=144B = 16*9 (16B-aligned rows)
#define GS 68   // smem row stride for epilogue gate tile

#define SA_STAGE (TM * AS)               // 4608 floats
#define SB_STAGE (TN * AS)               // 2304 floats
#define STAGE_FLOATS (SA_STAGE + SB_STAGE)
#define SMEM_FLOATS (STAGES * STAGE_FLOATS)
#define SMEM_BYTES (SMEM_FLOATS * 4)     // 82944 B

// -------- scratch (static device allocations; harness-legal) --------
__device__ float g_Wcat[(size_t)G4 * KTOT];    // 20 MB permuted weights, tf32-rounded
__device__ float g_bias[G4];
__device__ float g_xr[(size_t)B_ * T_ * I_];   // 134 MB: x pre-rounded to tf32
__device__ float g_h[2][(size_t)B_ * H_];      // ping-pong hidden state (tf32-rounded)
__device__ float g_c[(size_t)B_ * H_];         // cell state (full fp32)
__device__ float g_y1[(size_t)B_ * DEC1];

__device__ __forceinline__ unsigned f2tf(float f) {
    unsigned r;
    asm("cvt.rna.tf32.f32 %0, %1;" : "=r"(r) : "f"(f));
    return r;
}

__device__ __forceinline__ void cp_async16(void* smem_dst, const void* gsrc) {
    unsigned s = (unsigned)__cvta_generic_to_shared(smem_dst);
    asm volatile("cp.async.cg.shared.global [%0], [%1], 16;" :: "r"(s), "l"(gsrc));
}

// ====================================================================
// Prep kernels
// ====================================================================
__global__ void prep_w(const float* __restrict__ W_ih, const float* __restrict__ W_hh,
                       const float* __restrict__ b_ih, const float* __restrict__ b_hh) {
    int n = blockIdx.x;                 // 0..4095 (permuted row)
    int gate = n & 3, hcol = n >> 2;
    int src = gate * H_ + hcol;
    const float* wi = W_ih + (size_t)src * I_;
    const float* wh = W_hh + (size_t)src * H_;
    float* dst = g_Wcat + (size_t)n * KTOT;
    for (int k = threadIdx.x; k < KTOT; k += blockDim.x) {
        float v = (k < I_) ? wi[k] : wh[k - I_];
        dst[k] = __uint_as_float(f2tf(v));
    }
    if (threadIdx.x == 0) g_bias[n] = b_ih[src] + b_hh[src];
}

__global__ void prep_x(const float* __restrict__ x) {
    size_t n = (size_t)B_ * T_ * I_;
    for (size_t i = (size_t)blockIdx.x * blockDim.x + threadIdx.x; i < n;
         i += (size_t)gridDim.x * blockDim.x)
        g_xr[i] = __uint_as_float(f2tf(x[i]));
}

__global__ void prep_state(const float* __restrict__ h0, const float* __restrict__ c0) {
    int i = blockIdx.x * blockDim.x + threadIdx.x;
    if (i < B_ * H_) {
        g_h[0][i] = __uint_as_float(f2tf(h0[i]));   // h enters GEMMs tf32-rounded
        g_c[i] = c0[i];
    }
}

// ====================================================================
// One LSTM step: g = [x_t | h_prev] @ Wcat^T ; pointwise update fused.
// grid = (64 n-tiles, 2 m-tiles), 256 threads (8 warps as 4m x 2n of 32x32).
// 3-stage cp.async pipeline; TF32 mma.sync m16n8k8, fp32 accumulate.
// ====================================================================
__global__ __launch_bounds__(256) void lstm_step(int t, int pp) {
    extern __shared__ float sm[];

    const float* hprev = g_h[pp];
    float*       hnext = g_h[pp ^ 1];

    int tid   = threadIdx.x;
    int ntile = blockIdx.x;              // 0..63
    int mtile = blockIdx.y;              // 0..1
    int warp = tid >> 5, lane = tid & 31;
    int wm = warp & 3, wn = warp >> 2;
    int g  = lane >> 2, tg = lane & 3;

    int r8 = tid >> 3;                   // 0..31 (loader row base)
    int k4 = (tid & 7) * 4;              // 0..28 (loader k offset)

    // per-thread loader source bases
    const float* xbase[4];
    const float* hbase[4];
    const float* wbase[2];
    #pragma unroll
    for (int j = 0; j < 4; j++) {
        int b = mtile * TM + r8 + j * 32;
        xbase[j] = g_xr + ((size_t)b * T_ + t) * I_ + k4;
        hbase[j] = hprev + (size_t)b * H_ + k4;
    }
    #pragma unroll
    for (int j = 0; j < 2; j++) {
        int n = ntile * TN + r8 + j * 32;
        wbase[j] = g_Wcat + (size_t)n * KTOT + k4;
    }

    float acc[2][4][4];
    #pragma unroll
    for (int a = 0; a < 2; a++)
        #pragma unroll
        for (int b = 0; b < 4; b++)
            #pragma unroll
            for (int c = 0; c < 4; c++) acc[a][b][c] = 0.f;

    // ---- stage loader ----
    auto load_stage = [&](int stg, int kt) {
        float* As = sm + stg * STAGE_FLOATS;
        float* Bs = As + SA_STAGE;
        int k0 = kt * TK;
        if (k0 < I_) {
            #pragma unroll
            for (int j = 0; j < 4; j++)
                cp_async16(&As[(r8 + j * 32) * AS + k4], xbase[j] + k0);
        } else {
            #pragma unroll
            for (int j = 0; j < 4; j++)
                cp_async16(&As[(r8 + j * 32) * AS + k4], hbase[j] + (k0 - I_));
        }
        #pragma unroll
        for (int j = 0; j < 2; j++)
            cp_async16(&Bs[(r8 + j * 32) * AS + k4], wbase[j] + k0);
    };

    // prefetch first STAGES-1 stages
    load_stage(0, 0);
    asm volatile("cp.async.commit_group;");
    load_stage(1, 1);
    asm volatile("cp.async.commit_group;");

    int stg = 0;
    for (int kt = 0; kt < NKIT; kt++) {
        asm volatile("cp.async.wait_group 1;");
        __syncthreads();

        // prefetch stage kt+2 (overwrites stage consumed at kt-1; safe past the sync)
        int knext = kt + (STAGES - 1);
        if (knext < NKIT) load_stage((stg + STAGES - 1) % STAGES, knext);
        asm volatile("cp.async.commit_group;");

        // compute on stage stg
        float* As = sm + stg * STAGE_FLOATS;
        float* Bs = As + SA_STAGE;
        #pragma unroll
        for (int ks = 0; ks < 4; ks++) {
            int kk = ks * 8;
            unsigned af[2][4], bf[4][2];
            #pragma unroll
            for (int mi = 0; mi < 2; mi++) {
                int r0 = wm * 32 + mi * 16;
                af[mi][0] = __float_as_uint(As[(r0 + g    ) * AS + kk + tg    ]);
                af[mi][1] = __float_as_uint(As[(r0 + g + 8) * AS + kk + tg    ]);
                af[mi][2] = __float_as_uint(As[(r0 + g    ) * AS + kk + tg + 4]);
                af[mi][3] = __float_as_uint(As[(r0 + g + 8) * AS + kk + tg + 4]);
            }
            #pragma unroll
            for (int nj = 0; nj < 4; nj++) {
                int c0 = wn * 32 + nj * 8;
                bf[nj][0] = __float_as_uint(Bs[(c0 + g) * AS + kk + tg    ]);
                bf[nj][1] = __float_as_uint(Bs[(c0 + g) * AS + kk + tg + 4]);
            }
            #pragma unroll
            for (int mi = 0; mi < 2; mi++)
                #pragma unroll
                for (int nj = 0; nj < 4; nj++) {
                    asm volatile(
                        "mma.sync.aligned.m16n8k8.row.col.f32.tf32.tf32.f32 "
                        "{%0,%1,%2,%3}, {%4,%5,%6,%7}, {%8,%9}, {%0,%1,%2,%3};"
                        : "+f"(acc[mi][nj][0]), "+f"(acc[mi][nj][1]),
                          "+f"(acc[mi][nj][2]), "+f"(acc[mi][nj][3])
                        : "r"(af[mi][0]), "r"(af[mi][1]),
                          "r"(af[mi][2]), "r"(af[mi][3]),
                          "r"(bf[nj][0]), "r"(bf[nj][1]));
                }
        }
        stg = (stg + 1) % STAGES;
        __syncthreads();
    }

    // ---- spill gate tile to smem (128 x 64) ----
    float* Gs = sm;
    #pragma unroll
    for (int mi = 0; mi < 2; mi++) {
        int r0 = wm * 32 + mi * 16;
        #pragma unroll
        for (int nj = 0; nj < 4; nj++) {
            int c0 = wn * 32 + nj * 8 + tg * 2;
            Gs[(r0 + g    ) * GS + c0    ] = acc[mi][nj][0];
            Gs[(r0 + g    ) * GS + c0 + 1] = acc[mi][nj][1];
            Gs[(r0 + g + 8) * GS + c0    ] = acc[mi][nj][2];
            Gs[(r0 + g + 8) * GS + c0 + 1] = acc[mi][nj][3];
        }
    }
    __syncthreads();

    // ---- fused LSTM pointwise update: 128 rows x 16 hidden cols ----
    for (int it = tid; it < TM * 16; it += 256) {
        int r  = it >> 4;
        int j  = it & 15;
        int nl = 4 * j;
        int ng = ntile * TN + nl;
        float gi = Gs[r * GS + nl    ] + g_bias[ng    ];
        float gf = Gs[r * GS + nl + 1] + g_bias[ng + 1];
        float gg = Gs[r * GS + nl + 2] + g_bias[ng + 2];
        float go = Gs[r * GS + nl + 3] + g_bias[ng + 3];
        float iv = 1.f / (1.f + __expf(-gi));
        float fv = 1.f / (1.f + __expf(-gf));
        float gv = tanhf(gg);
        float ov = 1.f / (1.f + __expf(-go));
        int b  = mtile * TM + r;
        int hc = ntile * 16 + j;
        size_t idx = (size_t)b * H_ + hc;
        float c_new = fv * g_c[idx] + iv * gv;
        g_c[idx]   = c_new;
        hnext[idx] = __uint_as_float(f2tf(ov * tanhf(c_new)));
    }
}

// ====================================================================
// Decoder: y1 = h_T @ W1^T + b1 ; y = y1 @ W2^T + b2
// ====================================================================
__global__ void dec1(const float* __restrict__ W1, const float* __restrict__ b1) {
    __shared__ float hs[H_];
    int b = blockIdx.x;
    const float* h = g_h[0];   // after 512 steps the state is back in buffer 0
    for (int i = threadIdx.x; i < H_; i += blockDim.x) hs[i] = h[(size_t)b * H_ + i];
    __syncthreads();
    int warp = threadIdx.x >> 5, lane = threadIdx.x & 31;
    for (int m = warp; m < DEC1; m += 8) {
        const float* w = W1 + (size_t)m * H_;
        float s = 0.f;
        for (int k = lane; k < H_; k += 32) s += hs[k] * w[k];
        #pragma unroll
        for (int o = 16; o; o >>= 1) s += __shfl_down_sync(0xffffffffu, s, o);
        if (lane == 0) g_y1[(size_t)b * DEC1 + m] = s + b1[m];
    }
}

__global__ void dec2(const float* __restrict__ W2, const float* __restrict__ b2,
                     float* __restrict__ out) {
    int b = blockIdx.x;
    int warp = threadIdx.x >> 5, lane = threadIdx.x & 31;
    if (warp < OUT_) {
        const float* w = W2 + (size_t)warp * DEC1;
        const float* y = g_y1 + (size_t)b * DEC1;
        float s = 0.f;
        for (int k = lane; k < DEC1; k += 32) s += y[k] * w[k];
        #pragma unroll
        for (int o = 16; o; o >>= 1) s += __shfl_down_sync(0xffffffffu, s, o);
        if (lane == 0) out[b * OUT_ + warp] = s + b2[warp];
    }
}

// ====================================================================
extern "C" void kernel_launch(void* const* d_in, const int* in_sizes, int n_in,
                              void* d_out, int out_size) {
    const float* x    = (const float*)d_in[0];
    const float* h0   = (const float*)d_in[1];
    const float* c0   = (const float*)d_in[2];
    const float* W_ih = (const float*)d_in[3];
    const float* W_hh = (const float*)d_in[4];
    const float* b_ih = (const float*)d_in[5];
    const float* b_hh = (const float*)d_in[6];
    const float* W1   = (const float*)d_in[7];
    const float* b1   = (const float*)d_in[8];
    const float* W2   = (const float*)d_in[9];
    const float* b2   = (const float*)d_in[10];
    float* out = (float*)d_out;

    // host-side attribute set (idempotent; not a stream op, capture-legal)
    cudaFuncSetAttribute(lstm_step, cudaFuncAttributeMaxDynamicSharedMemorySize,
                         SMEM_BYTES);

    prep_w<<<G4, 256>>>(W_ih, W_hh, b_ih, b_hh);
    prep_x<<<2048, 256>>>(x);
    prep_state<<<(B_ * H_ + 511) / 512, 512>>>(h0, c0);

    dim3 grid(G4 / TN, B_ / TM);   // (64, 2)
    for (int t = 0; t < T_; t++)
        lstm_step<<<grid, 256, SMEM_BYTES>>>(t, t & 1);

    dec1<<<B_, 256>>>(W1, b1);
    dec2<<<B_, 128>>>(W2, b2, out);
}